// round 2
// baseline (speedup 1.0000x reference)
#include <cuda_runtime.h>
#include <math.h>

// Problem constants (fixed by dataset)
#define T_STEPS 2000
#define B_SZ    64
#define H_SZ    512
#define G4      2048
#define NCTA    128

// ---------------------------------------------------------------------------
// Device scratch (no allocations allowed anywhere)
// ---------------------------------------------------------------------------
__device__ float        g_s[H_SZ];                       // gate vector s[H]
__device__ unsigned int g_bar;                           // grid barrier counter
__device__ float        g_h[2][B_SZ * H_SZ];             // h double buffer (L2-resident)
__device__ float        g_gx[262144000];                 // [T*B, 4H] x-part of gates (1.05 GB)

// ---------------------------------------------------------------------------
// Packed f32x2 helpers (Blackwell FFMA2: PTX-only)
// ---------------------------------------------------------------------------
typedef unsigned long long ull;

__device__ __forceinline__ void fma2(ull& d, ull a, ull b) {
    asm("fma.rn.f32x2 %0, %1, %2, %0;" : "+l"(d) : "l"(a), "l"(b));
}
__device__ __forceinline__ void unpack2(ull v, float& x, float& y) {
    asm("mov.b64 {%0,%1}, %2;" : "=f"(x), "=f"(y) : "l"(v));
}

__device__ __forceinline__ float sigf(float x) {
    return 1.0f / (1.0f + __expf(-x));
}

// ---------------------------------------------------------------------------
// Prep: s = clip(sigmoid(log_alpha)*1.2 - 0.1, 0, 1); zero h0; reset barrier
// ---------------------------------------------------------------------------
__global__ void prep_kernel(const float* __restrict__ la) {
    int t = threadIdx.x;  // 512 threads
    float v = 1.0f / (1.0f + expf(-la[t]));
    v = v * 1.2f - 0.1f;
    v = fminf(fmaxf(v, 0.0f), 1.0f);
    g_s[t] = v;
    for (int i = t; i < B_SZ * H_SZ; i += 512) g_h[0][i] = 0.0f;
    if (t == 0) g_bar = 0u;
}

// ---------------------------------------------------------------------------
// GEMM: g_gx[m, r] = sum_k x[m,k]*s[k]*W[r,k] + b[r]
// 128x128 block tile, ktile 16, 256 threads, 8x8 microtile via f32x2.
// A staged pre-splatted (float2 {v,v}) so the inner loop has zero packing movs.
// ---------------------------------------------------------------------------
__global__ __launch_bounds__(256) void gemm_kernel(const float* __restrict__ X,
                                                   const float* __restrict__ W,
                                                   const float* __restrict__ bias) {
    __shared__ float2 As2[16 * 130];   // [k][row] pre-splatted, stride 130
    __shared__ float  Bs[16 * 132];    // [k][col(r)], stride 132

    int tid = threadIdx.x;
    int tx  = tid & 15;        // 16 col groups
    int ty  = tid >> 4;        // 16 row groups
    size_t m0 = (size_t)blockIdx.y * 128;
    int    n0 = blockIdx.x * 128;

    ull acc[8][4];
#pragma unroll
    for (int i = 0; i < 8; ++i)
#pragma unroll
        for (int j = 0; j < 4; ++j) acc[i][j] = 0ull;

    for (int kt = 0; kt < 512; kt += 16) {
#pragma unroll
        for (int i = 0; i < 2; ++i) {
            int f4  = tid + 256 * i;        // 0..511
            int row = f4 >> 2;              // 0..127
            int kq  = f4 & 3;               // 0..3 (4 k's each)
            float4 av = *(const float4*)&X[(m0 + row) * 512 + kt + kq * 4];
            float4 wv = *(const float4*)&W[((size_t)(n0 + row)) * 512 + kt + kq * 4];
            float s0 = g_s[kt + kq * 4 + 0];
            float s1 = g_s[kt + kq * 4 + 1];
            float s2 = g_s[kt + kq * 4 + 2];
            float s3 = g_s[kt + kq * 4 + 3];
            float a0 = av.x * s0, a1 = av.y * s1, a2 = av.z * s2, a3 = av.w * s3;
            As2[(kq * 4 + 0) * 130 + row] = make_float2(a0, a0);
            As2[(kq * 4 + 1) * 130 + row] = make_float2(a1, a1);
            As2[(kq * 4 + 2) * 130 + row] = make_float2(a2, a2);
            As2[(kq * 4 + 3) * 130 + row] = make_float2(a3, a3);
            Bs[(kq * 4 + 0) * 132 + row] = wv.x;
            Bs[(kq * 4 + 1) * 132 + row] = wv.y;
            Bs[(kq * 4 + 2) * 132 + row] = wv.z;
            Bs[(kq * 4 + 3) * 132 + row] = wv.w;
        }
        __syncthreads();

#pragma unroll
        for (int kk = 0; kk < 16; ++kk) {
            ull a2r[8], b2r[4];
#pragma unroll
            for (int i = 0; i < 8; ++i)
                a2r[i] = *(const ull*)&As2[kk * 130 + ty * 8 + i];
#pragma unroll
            for (int jp = 0; jp < 4; ++jp)
                b2r[jp] = *(const ull*)&Bs[kk * 132 + 2 * tx + 32 * jp];
#pragma unroll
            for (int i = 0; i < 8; ++i)
#pragma unroll
                for (int jp = 0; jp < 4; ++jp)
                    fma2(acc[i][jp], a2r[i], b2r[jp]);
        }
        __syncthreads();
    }

    // epilogue: + bias, store pairs
#pragma unroll
    for (int jp = 0; jp < 4; ++jp) {
        float2 bb = *(const float2*)&bias[n0 + 2 * tx + 32 * jp];
#pragma unroll
        for (int i = 0; i < 8; ++i) {
            float ax, ay;
            unpack2(acc[i][jp], ax, ay);
            float2 o = make_float2(ax + bb.x, ay + bb.y);
            *(float2*)&g_gx[(m0 + ty * 8 + i) * 2048 + n0 + 2 * tx + 32 * jp] = o;
        }
    }
}

// ---------------------------------------------------------------------------
// Persistent recurrent kernel: 128 CTAs x 256 threads, 4 hidden units per CTA.
// SMEM: h (skewed), U_hat slice (skewed), gate stage, h-out stage.
// Thread tiling for the dot: ks = tid&7 (k-split 8), btile = (tid>>3)&7 (8 b),
// rtile = tid>>6 (4 rows each).
// ---------------------------------------------------------------------------
#define SH   530                    // h row stride (floats); SH/2 = 265 odd
#define SU   528                    // U row stride
#define SST  66                     // gate stage row stride
#define HS_F (64 * SH)              // 33920
#define US_F (16 * SU)              // 8448
#define ST_F (16 * SST)             // 1056
#define SMEM_FLOATS (HS_F + US_F + ST_F + 256)

__global__ void __launch_bounds__(256, 1)
lstm_kernel(const float* __restrict__ U, float* __restrict__ out) {
    extern __shared__ float sm[];
    float* h_s = sm;
    float* U_s = sm + HS_F;
    float* stg = sm + HS_F + US_F;
    float* st2 = sm + HS_F + US_F + ST_F;

    int tid = threadIdx.x;
    int u0  = blockIdx.x * 4;

    // ---- load U_hat slice (once). Row order lr = gate*4 + unit.
    for (int i = 0; i < 32; ++i) {
        int idx = tid + 256 * i;          // 0..8191
        int lr  = idx >> 9;               // 0..15
        int k   = idx & 511;
        int gg  = lr >> 2;
        int uu  = lr & 3;
        float v = U[((size_t)(gg * 512 + u0 + uu)) * 512 + k] * g_s[u0 + uu] * g_s[k];
        U_s[lr * SU + (k >> 6) * 66 + (k & 63)] = v;
    }

    // dot-phase ids
    int ks    = tid & 7;
    int btile = (tid >> 3) & 7;
    int rtile = tid >> 6;
    int b0    = btile * 8;
    int r0    = rtile * 4;
    int koff  = ks * 66;

    // combine-phase ids (cell per thread)
    int cu = tid >> 6;     // unit 0..3
    int cb = tid & 63;     // batch 0..63
    float c_state = 0.0f;

    // h staging ids
    int schunk  = tid >> 5;
    int swin    = tid & 31;
    int sts_off = schunk * 66 + 2 * swin;

    __syncthreads();

    unsigned bar_target = 0;
    for (int t = 0; t < T_STEPS; ++t) {
        const float* hin  = g_h[t & 1];
        float*       hout = g_h[(t + 1) & 1];

        // prefetch gx for combine (consumed ~8k cycles later)
        size_t gxb = ((size_t)t * 64 + cb) * 2048 + u0 + cu;
        float gx0 = g_gx[gxb];
        float gx1 = g_gx[gxb + 512];
        float gx2 = g_gx[gxb + 1024];
        float gx3 = g_gx[gxb + 1536];

        // ---- stage h: global [b][k] (f32x2 over k) -> skewed smem
        {
            const ull* src = (const ull*)hin;   // index b*256 + k2, k2 = tid
#pragma unroll 8
            for (int b = 0; b < 64; ++b) {
                ull v = src[(size_t)b * 256 + tid];
                *(ull*)&h_s[b * SH + sts_off] = v;
            }
        }
        __syncthreads();

        // ---- dot: acc[bb][rr] over this thread's 64-wide k chunk, f32x2 pairs
        ull acc[8][4];
#pragma unroll
        for (int i = 0; i < 8; ++i)
#pragma unroll
            for (int j = 0; j < 4; ++j) acc[i][j] = 0ull;

#pragma unroll 8
        for (int kp = 0; kp < 32; ++kp) {
            ull hv[8], uv[4];
#pragma unroll
            for (int bb = 0; bb < 8; ++bb)
                hv[bb] = *(const ull*)&h_s[(b0 + bb) * SH + koff + 2 * kp];
#pragma unroll
            for (int rr = 0; rr < 4; ++rr)
                uv[rr] = *(const ull*)&U_s[(r0 + rr) * SU + koff + 2 * kp];
#pragma unroll
            for (int bb = 0; bb < 8; ++bb)
#pragma unroll
                for (int rr = 0; rr < 4; ++rr)
                    fma2(acc[bb][rr], hv[bb], uv[rr]);
        }

        // ---- reduce over the 8-way k-split (lanes differing in bits 0..2)
        float v[8][4];
#pragma unroll
        for (int bb = 0; bb < 8; ++bb)
#pragma unroll
            for (int rr = 0; rr < 4; ++rr) {
                float x, y;
                unpack2(acc[bb][rr], x, y);
                v[bb][rr] = x + y;
            }
#pragma unroll
        for (int off = 1; off < 8; off <<= 1)
#pragma unroll
            for (int bb = 0; bb < 8; ++bb)
#pragma unroll
                for (int rr = 0; rr < 4; ++rr)
                    v[bb][rr] += __shfl_xor_sync(0xffffffffu, v[bb][rr], off);

        if (ks == 0) {
#pragma unroll
            for (int rr = 0; rr < 4; ++rr)
#pragma unroll
                for (int bb = 0; bb < 8; ++bb)
                    stg[(r0 + rr) * SST + b0 + bb] = v[bb][rr];
        }
        __syncthreads();

        // ---- combine: one (unit,batch) cell per thread
        float zi = stg[(0 * 4 + cu) * SST + cb] + gx0;
        float zf = stg[(1 * 4 + cu) * SST + cb] + gx1;
        float zg = stg[(2 * 4 + cu) * SST + cb] + gx2;
        float zo = stg[(3 * 4 + cu) * SST + cb] + gx3;
        float ig = sigf(zi);
        float fg = sigf(zf);
        float gg = tanhf(zg);
        float og = sigf(zo);
        float cn = fg * c_state + ig * gg;
        c_state  = cn;
        float hn = og * tanhf(cn);

        hout[cb * 512 + u0 + cu] = hn;     // L2-resident scatter (small)
        st2[cb * 4 + cu] = hn;
        __syncthreads();

        // output write, 16B per batch row
        if (tid < 64) {
            float4 h4 = *(float4*)&st2[tid * 4];
            *(float4*)&out[((size_t)t * 64 + tid) * 512 + u0] = h4;
        }

        // ---- grid barrier (monotone counter; reset each launch by prep)
        bar_target += NCTA;
        __syncthreads();
        if (tid == 0) {
            __threadfence();
            atomicAdd(&g_bar, 1u);
            while (*(volatile unsigned*)&g_bar < bar_target) { }
            __threadfence();
        }
        __syncthreads();
    }
}

// ---------------------------------------------------------------------------
extern "C" void kernel_launch(void* const* d_in, const int* in_sizes, int n_in,
                              void* d_out, int out_size) {
    const float* x  = (const float*)d_in[0];
    const float* W  = (const float*)d_in[1];
    const float* U  = (const float*)d_in[2];
    const float* b  = (const float*)d_in[3];
    const float* la = (const float*)d_in[4];
    float* out = (float*)d_out;

    prep_kernel<<<1, 512>>>(la);

    dim3 ggrid(16, 1000);
    gemm_kernel<<<ggrid, 256>>>(x, W, b);

    cudaFuncSetAttribute(lstm_kernel, cudaFuncAttributeMaxDynamicSharedMemorySize,
                         SMEM_FLOATS * 4);
    lstm_kernel<<<NCTA, 256, SMEM_FLOATS * 4>>>(U, out);
}